// round 11
// baseline (speedup 1.0000x reference)
#include <cuda_runtime.h>
#include <cstdint>

#define K_DIM   5120
#define E_DIM   5120
#define N_NODES 27
#define HD      1280

// ---- scratch (device globals; no allocations allowed) ----
__device__ float    g_qkvT[15360 * 28];    // qkv transposed [3E][28]
__device__ float    g_colrow[54];
__device__ float    g_scores[4 * 729];
__device__ float    g_attn[4 * 729];
__device__ int      g_cnt;
__device__ int      g_flag;
// B operand in MMA-fragment order: [k16 (320)][lane (32)][frag (8 = nt*2+reg)]
__device__ uint32_t g_bhi[320 * 256];
__device__ uint32_t g_blo[320 * 256];

static __device__ __forceinline__ float hw_from(const int* lh) {
    int iv = *lh;
    float f = (iv > 0 && iv < 100000000) ? (float)iv : __int_as_float(iv);
    return fminf(fmaxf(f * 0.001f, 0.1f), 1.0f);
}

static __device__ __forceinline__ uint32_t smem_u32(const void* p) {
    uint32_t a;
    asm("{ .reg .u64 t; cvta.to.shared.u64 t, %1; cvt.u32.u64 %0, t; }" : "=r"(a) : "l"(p));
    return a;
}

// Split f32 pair -> bf16x2 hi (exact truncation) + bf16x2 lo (rounded remainder).
static __device__ __forceinline__ void split_pack(float f0, float f1,
                                                  uint32_t& hi, uint32_t& lo) {
    uint32_t u0 = __float_as_uint(f0), u1 = __float_as_uint(f1);
    asm("prmt.b32 %0, %1, %2, 0x7632;" : "=r"(hi) : "r"(u0), "r"(u1));
    float l0 = f0 - __uint_as_float(u0 & 0xFFFF0000u);
    float l1 = f1 - __uint_as_float(u1 & 0xFFFF0000u);
    asm("cvt.rn.bf16x2.f32 %0, %1, %2;" : "=r"(lo) : "f"(l1), "f"(l0));
}

#define MMA_BF16(d, a, b0, b1)                                                  \
    asm volatile(                                                               \
        "mma.sync.aligned.m16n8k16.row.col.f32.bf16.bf16.f32 "                  \
        "{%0,%1,%2,%3}, {%4,%5,%6,%7}, {%8,%9}, {%0,%1,%2,%3};"                 \
        : "+f"((d)[0]), "+f"((d)[1]), "+f"((d)[2]), "+f"((d)[3])                \
        : "r"((a)[0]), "r"((a)[1]), "r"((a)[2]), "r"((a)[3]),                   \
          "r"(b0), "r"(b1))

#define CP_ASYNC16(saddr, gptr)                                                 \
    asm volatile("cp.async.cg.shared.global [%0], [%1], 16;"                    \
                 :: "r"(saddr), "l"(gptr))
#define CP_COMMIT()  asm volatile("cp.async.commit_group;" ::: "memory")
#define CP_WAIT2()   asm volatile("cp.async.wait_group 2;" ::: "memory")

// =====================================================================
// Fragment prep for X (27 x 5120): b-frag for m16n8k16:
//   frag f = nt*2+reg: value = X[n = nt*8 + lane>>2][k0, k0+1],
//   k0 = k16*16 + reg*8 + 2*(lane&3).  Layout [k16][lane][f].
// =====================================================================
static __device__ __forceinline__ void prep_body(const float* __restrict__ src, int t4)
{
    int lane = t4 & 31;
    int f    = (t4 >> 5) & 7;
    int k16b = (t4 >> 8) * 4;
    int reg  = f & 1;
    int nt   = f >> 1;
    int n    = nt * 8 + (lane >> 2);
    const bool ok = (n < N_NODES);
    const float* row = src + (size_t)n * K_DIM;
    float f0[4], f1[4];
    #pragma unroll
    for (int u = 0; u < 4; u++) {
        int k0 = (k16b + u) * 16 + reg * 8 + 2 * (lane & 3);
        f0[u] = ok ? row[k0]     : 0.0f;
        f1[u] = ok ? row[k0 + 1] : 0.0f;
    }
    #pragma unroll
    for (int u = 0; u < 4; u++) {
        uint32_t hi, lo;
        split_pack(f0[u], f1[u], hi, lo);
        int idx = (k16b + u) * 256 + lane * 8 + f;
        g_bhi[idx] = hi;
        g_blo[idx] = lo;
    }
}

// =====================================================================
// pre: blocks [0,80) prep node frags | [80,134) granger dots | rest init
// =====================================================================
__global__ __launch_bounds__(256)
void pre_kernel(const float* __restrict__ node, const float* __restrict__ hist,
                const float* __restrict__ gw, const float* __restrict__ inb,
                const float* __restrict__ outb, const int* __restrict__ lh,
                float* __restrict__ out)
{
    const int bx = blockIdx.x;
    const int tid = threadIdx.x;

    if (bx < 80) { prep_body(node, bx * 256 + tid); return; }

    if (bx < 134) {   // granger dot b (0..53)
        const int b = bx - 80;
        const float* x  = (b < 27) ? node + (size_t)b * E_DIM : hist + (size_t)(b - 27) * E_DIM;
        const float* wv = (b < 27) ? gw + E_DIM : gw;
        float s = 0.0f;
        for (int k = tid; k < E_DIM; k += 256) s += x[k] * wv[k];
        __shared__ float sred[8];
        #pragma unroll
        for (int off = 16; off; off >>= 1) s += __shfl_xor_sync(0xffffffffu, s, off);
        if ((tid & 31) == 0) sred[tid >> 5] = s;
        __syncthreads();
        if (tid < 8) {
            s = sred[tid];
            #pragma unroll
            for (int off = 4; off; off >>= 1) s += __shfl_xor_sync(0x000000ffu, s, off);
            if (tid == 0) g_colrow[b] = s;
        }
        return;
    }

    int t = (bx - 134) * 256 + tid;
    if (t < 15360 * 27) {                       // qkvT bias seed
        int m = t / 27, n = t - m * 27;
        g_qkvT[m * 28 + n] = inb[m];
    } else if (t < 15360 * 27 + 27 * 5120) {    // out bias*hw seed
        int t2 = t - 15360 * 27;
        out[t2] = outb[t2 % 5120] * hw_from(lh);
    } else if (t < 15360 * 27 + 27 * 5120 + 4 * 729) {
        g_scores[t - (15360 * 27 + 27 * 5120)] = 0.0f;
    } else if (t == 15360 * 27 + 27 * 5120 + 4 * 729) {
        g_cnt = 0;
        g_flag = 0;
    }
}

// =====================================================================
// HMMA split-K GEMM, cp.async A pipeline, warp-private stages:
//   D[m][n] = sum_k W[m][k] * X[n][k]
//   128 thr = 4 warps x 64 rows = 256 rows/CTA.
//   A: 3-stage per-warp smem ring via cp.async (stage = 64 rows x 128B
//      = 2 k16), XOR swizzle (c ^= (r&3)<<1) -> conflict-free LDS.64.
//   B: dist-1 register prefetch from L2 frags (LDG.128 x4).
//   No __syncthreads in mainloop; only wait_group + __syncwarp.
// =====================================================================
template<int KK>
static __device__ __forceinline__ void kstep(
    int i, int nk16, int k16_0, uint32_t sb, int lane, int r, int t2,
    uint32_t (&Bh)[2][8], uint32_t (&Bl)[2][8], float (&acc)[4][4][4])
{
    constexpr int BUF  = KK;       // i parity == KK (stages start at even k16)
    constexpr int NBUF = KK ^ 1;
    // B prefetch for i+1 (L2 hit, one full k16 of slack)
    if (i + 1 < nk16) {
        const uint32_t* ph = g_bhi + (size_t)(k16_0 + i + 1) * 256 + lane * 8;
        const uint32_t* pl = g_blo + (size_t)(k16_0 + i + 1) * 256 + lane * 8;
        uint4 h0 = *(const uint4*)ph, h1 = *(const uint4*)(ph + 4);
        uint4 l0 = *(const uint4*)pl, l1 = *(const uint4*)(pl + 4);
        Bh[NBUF][0] = h0.x; Bh[NBUF][1] = h0.y; Bh[NBUF][2] = h0.z; Bh[NBUF][3] = h0.w;
        Bh[NBUF][4] = h1.x; Bh[NBUF][5] = h1.y; Bh[NBUF][6] = h1.z; Bh[NBUF][7] = h1.w;
        Bl[NBUF][0] = l0.x; Bl[NBUF][1] = l0.y; Bl[NBUF][2] = l0.z; Bl[NBUF][3] = l0.w;
        Bl[NBUF][4] = l1.x; Bl[NBUF][5] = l1.y; Bl[NBUF][6] = l1.z; Bl[NBUF][7] = l1.w;
    }
    // A from smem stage + convert
    uint32_t ahi[4][4], alo[4][4];
    #pragma unroll
    for (int mf = 0; mf < 4; mf++)
        #pragma unroll
        for (int kc = 0; kc < 2; kc++)
            #pragma unroll
            for (int rr = 0; rr < 2; rr++) {
                const int row = mf * 16 + rr * 8 + r;
                const int kb  = KK * 64 + kc * 32 + t2 * 4;
                const int chunk = kb >> 4;
                uint32_t a = sb + row * 128 + ((chunk ^ ((r & 3) << 1)) << 4) + (kb & 15);
                float2 v;
                asm volatile("ld.shared.v2.f32 {%0,%1}, [%2];"
                             : "=f"(v.x), "=f"(v.y) : "r"(a));
                split_pack(v.x, v.y, ahi[mf][kc * 2 + rr], alo[mf][kc * 2 + rr]);
            }
    #pragma unroll
    for (int mf = 0; mf < 4; mf++)
        #pragma unroll
        for (int nt = 0; nt < 4; nt++) {
            MMA_BF16(acc[mf][nt], ahi[mf], Bh[BUF][nt * 2], Bh[BUF][nt * 2 + 1]);
            MMA_BF16(acc[mf][nt], ahi[mf], Bl[BUF][nt * 2], Bl[BUF][nt * 2 + 1]);
            MMA_BF16(acc[mf][nt], alo[mf], Bh[BUF][nt * 2], Bh[BUF][nt * 2 + 1]);
        }
}

__global__ __launch_bounds__(128, 2)
void gemm_hmma(const float* __restrict__ W, float* __restrict__ dst,
               int mode, int spl16, const int* __restrict__ lh)
{
    extern __shared__ uint32_t smem[];   // 4 warps x 3 stages x 8KB = 96KB

    const int tid  = threadIdx.x;
    const int lane = tid & 31;
    const int wid  = tid >> 5;
    const int mbase = blockIdx.x * 256 + wid * 64;
    const int k16_0 = blockIdx.y * spl16;
    const int nk16  = min(spl16, 320 - k16_0);
    const int nst   = nk16 >> 1;         // stages, 2 k16 each (splits are even)
    const int r  = lane >> 2;
    const int t2 = (lane & 3) * 2;
    const uint32_t wsm = smem_u32(smem) + wid * 24576;

    // writer: thread covers rows lane and lane+32 of the warp's 64-row slice
    const float* wrow0 = W + (size_t)(mbase + lane) * K_DIM + (size_t)k16_0 * 16;
    const float* wrow1 = wrow0 + (size_t)32 * K_DIM;
    const uint32_t swz = ((uint32_t)(lane & 3)) << 1;   // (row&3)<<1, same both rows

    auto issue_stage = [&](int s) {
        if (s < nst) {
            const uint32_t b0 = wsm + (uint32_t)(s % 3) * 8192 + lane * 128;
            const uint32_t b1 = b0 + 32 * 128;
            const float* g0 = wrow0 + (size_t)s * 32;
            const float* g1 = wrow1 + (size_t)s * 32;
            #pragma unroll
            for (int c = 0; c < 8; c++)
                CP_ASYNC16(b0 + ((c ^ swz) << 4), g0 + c * 4);
            #pragma unroll
            for (int c = 0; c < 8; c++)
                CP_ASYNC16(b1 + ((c ^ swz) << 4), g1 + c * 4);
        }
        CP_COMMIT();
    };

    float acc[4][4][4];
    #pragma unroll
    for (int mf = 0; mf < 4; mf++)
        #pragma unroll
        for (int nt = 0; nt < 4; nt++)
            #pragma unroll
            for (int q = 0; q < 4; q++) acc[mf][nt][q] = 0.0f;

    uint32_t Bh[2][8], Bl[2][8];

    // prologue: stages 0..2 in flight; B(k16_0) -> buf0
    issue_stage(0); issue_stage(1); issue_stage(2);
    {
        const uint32_t* ph = g_bhi + (size_t)k16_0 * 256 + lane * 8;
        const uint32_t* pl = g_blo + (size_t)k16_0 * 256 + lane * 8;
        uint4 h0 = *(const uint4*)ph, h1 = *(const uint4*)(ph + 4);
        uint4 l0 = *(const uint4*)pl, l1 = *(const uint4*)(pl + 4);
        Bh[0][0] = h0.x; Bh[0][1] = h0.y; Bh[0][2] = h0.z; Bh[0][3] = h0.w;
        Bh[0][4] = h1.x; Bh[0][5] = h1.y; Bh[0][6] = h1.z; Bh[0][7] = h1.w;
        Bl[0][0] = l0.x; Bl[0][1] = l0.y; Bl[0][2] = l0.z; Bl[0][3] = l0.w;
        Bl[0][4] = l1.x; Bl[0][5] = l1.y; Bl[0][6] = l1.z; Bl[0][7] = l1.w;
    }

    for (int s = 0; s < nst; s++) {
        CP_WAIT2();          // stage s landed (<=2 groups still pending)
        __syncwarp();
        const uint32_t sb = wsm + (uint32_t)(s % 3) * 8192;
        const int i = s * 2;
        kstep<0>(i,     nk16, k16_0, sb, lane, r, t2, Bh, Bl, acc);
        kstep<1>(i + 1, nk16, k16_0, sb, lane, r, t2, Bh, Bl, acc);
        __syncwarp();        // all lanes done reading stage s before refill
        issue_stage(s + 3);
    }

    // epilogue: d0=(m0,n0) d1=(m0,n0+1) d2=(m0+8,n0) d3=(m0+8,n0+1)
    if (mode == 0) {
        #pragma unroll
        for (int mf = 0; mf < 4; mf++) {
            int m0 = mbase + mf * 16 + r;
            #pragma unroll
            for (int nt = 0; nt < 4; nt++) {
                int n0 = nt * 8 + t2;
                if (n0 < N_NODES)     atomicAdd(&g_qkvT[m0 * 28 + n0],           acc[mf][nt][0]);
                if (n0 + 1 < N_NODES) atomicAdd(&g_qkvT[m0 * 28 + n0 + 1],       acc[mf][nt][1]);
                if (n0 < N_NODES)     atomicAdd(&g_qkvT[(m0 + 8) * 28 + n0],     acc[mf][nt][2]);
                if (n0 + 1 < N_NODES) atomicAdd(&g_qkvT[(m0 + 8) * 28 + n0 + 1], acc[mf][nt][3]);
            }
        }
    } else {
        const float hw = hw_from(lh);
        #pragma unroll
        for (int mf = 0; mf < 4; mf++) {
            int m0 = mbase + mf * 16 + r;
            #pragma unroll
            for (int nt = 0; nt < 4; nt++) {
                int n0 = nt * 8 + t2;
                if (n0 < N_NODES)     atomicAdd(&dst[(size_t)n0 * E_DIM + m0],           acc[mf][nt][0] * hw);
                if (n0 + 1 < N_NODES) atomicAdd(&dst[(size_t)(n0 + 1) * E_DIM + m0],     acc[mf][nt][1] * hw);
                if (n0 < N_NODES)     atomicAdd(&dst[(size_t)n0 * E_DIM + m0 + 8],       acc[mf][nt][2] * hw);
                if (n0 + 1 < N_NODES) atomicAdd(&dst[(size_t)(n0 + 1) * E_DIM + m0 + 8], acc[mf][nt][3] * hw);
            }
        }
    }
}

// =====================================================================
// Fused attention: scores partials -> counter -> last-block softmax+adj
// -> flag -> all blocks AV + GEMM2 fragment emission.
// grid (10,4); 40 blocks << 148 SMs -> all resident, spin-wait safe.
// =====================================================================
__global__ __launch_bounds__(256)
void attn_fused(const float* __restrict__ gb, float* __restrict__ out)
{
    const int ct = blockIdx.x;   // 0..9
    const int h  = blockIdx.y;   // 0..3
    __shared__ float sA[128 * 29];   // q tile, then v tile
    __shared__ float sB[128 * 29];   // k tile, then o (stride 28)
    __shared__ float sa[729];
    const int tid = threadIdx.x;

    const float4* qb = (const float4*)(g_qkvT + (size_t)(h * HD + ct * 128) * 28);
    const float4* kb = (const float4*)(g_qkvT + (size_t)(E_DIM + h * HD + ct * 128) * 28);
    for (int idx = tid; idx < 896; idx += 256) {
        int c = idx / 7, r4 = idx - c * 7;
        float4 q4 = qb[idx], k4 = kb[idx];
        int b = c * 29 + r4 * 4;
        sA[b] = q4.x; sA[b + 1] = q4.y; sA[b + 2] = q4.z; sA[b + 3] = q4.w;
        sB[b] = k4.x; sB[b + 1] = k4.y; sB[b + 2] = k4.z; sB[b + 3] = k4.w;
    }
    __syncthreads();

    for (int t = tid; t < 729; t += 256) {
        int i = t / 27, j = t - i * 27;
        float s0 = 0.0f, s1 = 0.0f;
        #pragma unroll
        for (int c = 0; c < 128; c += 2) {
            s0 += sA[c * 29 + i] * sB[c * 29 + j];
            s1 += sA[(c + 1) * 29 + i] * sB[(c + 1) * 29 + j];
        }
        atomicAdd(&g_scores[h * 729 + t], s0 + s1);
    }
    __threadfence();
    __syncthreads();

    __shared__ int isLast;
    if (tid == 0) isLast = (atomicAdd(&g_cnt, 1) == 39);
    __syncthreads();

    // overwrite sA with V tile while waiting (q/k no longer needed)
    const float4* vb = (const float4*)(g_qkvT + (size_t)(2 * E_DIM + h * HD + ct * 128) * 28);
    for (int idx = tid; idx < 896; idx += 256) {
        int c = idx / 7, r4 = idx - c * 7;
        float4 v4 = vb[idx];
        int b = c * 29 + r4 * 4;
        sA[b] = v4.x; sA[b + 1] = v4.y; sA[b + 2] = v4.z; sA[b + 3] = v4.w;
    }

    if (isLast) {
        if (tid < 108) {   // softmax per (head, query)
            const int hh = tid / 27, i = tid - hh * 27;
            const float scale = rsqrtf((float)HD);
            const float* sc = g_scores + hh * 729 + i * 27;
            float mx = -1e30f;
            #pragma unroll
            for (int j = 0; j < 27; j++) mx = fmaxf(mx, sc[j] * scale);
            float e[27], sum = 0.0f;
            #pragma unroll
            for (int j = 0; j < 27; j++) { e[j] = expf(sc[j] * scale - mx); sum += e[j]; }
            const float inv = 1.0f / sum;
            float* at = g_attn + hh * 729 + i * 27;
            #pragma unroll
            for (int j = 0; j < 27; j++) at[j] = e[j] * inv;
        }
        for (int idx = tid; idx < 729; idx += 256) {   // causal adjacency
            int i = idx / 27, j = idx - i * 27;
            float v = 0.0f;
            if (i != j)
                v = 1.0f / (1.0f + expf(-(g_colrow[i] + g_colrow[27 + j] + gb[0])));
            out[N_NODES * E_DIM + idx] = v;
        }
        __syncthreads();
        __threadfence();
        if (tid == 0) *(volatile int*)&g_flag = 1;
    }

    if (tid == 0) { while (*(volatile int*)&g_flag == 0) { } }
    __syncthreads();
    __threadfence();

    for (int idx = tid; idx < 729; idx += 256) sa[idx] = g_attn[h * 729 + idx];
    __syncthreads();

    // AV into sB (o[c][i], stride 28)
    for (int f = tid; f < 27 * 128; f += 256) {
        int c = f & 127, i = f >> 7;
        float o = 0.0f;
        #pragma unroll
        for (int j = 0; j < 27; j++) o += sa[i * 27 + j] * sA[c * 29 + j];
        sB[c * 28 + i] = o;
    }
    __syncthreads();

    // GEMM2 fragment emission ([k16][lane][f] layout)
    const int k16g0 = (h * HD + ct * 128) >> 4;
    const int lane = tid & 31;
    const int f    = tid >> 5;          // 0..7
    const int nt   = f >> 1, reg = f & 1;
    const int n    = nt * 8 + (lane >> 2);
    const int cb   = reg * 8 + 2 * (lane & 3);
    const bool ok  = (n < N_NODES);
    #pragma unroll
    for (int k16l = 0; k16l < 8; k16l++) {
        int c = k16l * 16 + cb;
        float f0 = ok ? sB[c * 28 + n]       : 0.0f;
        float f1 = ok ? sB[(c + 1) * 28 + n] : 0.0f;
        uint32_t hi, lo;
        split_pack(f0, f1, hi, lo);
        int idx = (k16g0 + k16l) * 256 + lane * 8 + f;
        g_bhi[idx] = hi;
        g_blo[idx] = lo;
    }
}

// =====================================================================
extern "C" void kernel_launch(void* const* d_in, const int* in_sizes, int n_in,
                              void* d_out, int out_size)
{
    const float* node = (const float*)d_in[0];
    const float* hist = (const float*)d_in[1];
    const float* gw   = (const float*)d_in[2];
    const float* gb   = (const float*)d_in[3];
    const float* inw  = (const float*)d_in[4];
    const float* inb  = (const float*)d_in[5];
    const float* outw = (const float*)d_in[6];
    const float* outb = (const float*)d_in[7];
    const int*   lh   = (const int*)d_in[8];
    float* out = (float*)d_out;

    cudaFuncSetAttribute(gemm_hmma, cudaFuncAttributeMaxDynamicSharedMemorySize, 98304);

    const int init_elems = 15360 * 27 + 27 * 5120 + 4 * 729 + 1;
    const int init_blocks = (init_elems + 255) / 256;
    pre_kernel<<<134 + init_blocks, 256>>>(node, hist, gw, inb, outb, lh, out);

    // qkv += x @ in_proj_w^T : 60 M-tiles (256 rows) x 4 K-splits (80 k16)
    gemm_hmma<<<dim3(60, 4), 128, 98304>>>(inw, nullptr, 0, 80, lh);

    attn_fused<<<dim3(10, 4), 256>>>(gb, out);

    // out += (o @ out_proj_w^T) * hw : 20 M-tiles x 10 K-splits (32 k16)
    gemm_hmma<<<dim3(20, 10), 128, 98304>>>(outw, out, 1, 32, lh);
}

// round 12
// speedup vs baseline: 1.5023x; 1.5023x over previous
#include <cuda_runtime.h>
#include <cstdint>

#define K_DIM   5120
#define E_DIM   5120
#define N_NODES 27
#define HD      1280

// ---- scratch (device globals; no allocations allowed) ----
__device__ float    g_qkvT[15360 * 28];    // qkv transposed [3E][28]
__device__ float    g_colrow[54];
__device__ float    g_scores[4 * 729];
__device__ float    g_attn[4 * 729];
__device__ int      g_cnt;
__device__ int      g_flag;
// B operand in MMA-fragment order: [k16 (320)][lane (32)][frag (8 = nt*2+reg)]
__device__ uint32_t g_bhi[320 * 256];
__device__ uint32_t g_blo[320 * 256];

static __device__ __forceinline__ float hw_from(const int* lh) {
    int iv = *lh;
    float f = (iv > 0 && iv < 100000000) ? (float)iv : __int_as_float(iv);
    return fminf(fmaxf(f * 0.001f, 0.1f), 1.0f);
}

// Split f32 pair -> bf16x2 hi (exact truncation) + bf16x2 lo (rounded remainder).
static __device__ __forceinline__ void split_pack(float f0, float f1,
                                                  uint32_t& hi, uint32_t& lo) {
    uint32_t u0 = __float_as_uint(f0), u1 = __float_as_uint(f1);
    asm("prmt.b32 %0, %1, %2, 0x7632;" : "=r"(hi) : "r"(u0), "r"(u1));
    float l0 = f0 - __uint_as_float(u0 & 0xFFFF0000u);
    float l1 = f1 - __uint_as_float(u1 & 0xFFFF0000u);
    asm("cvt.rn.bf16x2.f32 %0, %1, %2;" : "=r"(lo) : "f"(l1), "f"(l0));
}

#define MMA_BF16(d, a, b0, b1)                                                  \
    asm volatile(                                                               \
        "mma.sync.aligned.m16n8k16.row.col.f32.bf16.bf16.f32 "                  \
        "{%0,%1,%2,%3}, {%4,%5,%6,%7}, {%8,%9}, {%0,%1,%2,%3};"                 \
        : "+f"((d)[0]), "+f"((d)[1]), "+f"((d)[2]), "+f"((d)[3])                \
        : "r"((a)[0]), "r"((a)[1]), "r"((a)[2]), "r"((a)[3]),                   \
          "r"(b0), "r"(b1))

// =====================================================================
// Fragment prep for X (27 x 5120): b-frag for m16n8k16:
//   frag f = nt*2+reg: value = X[n = nt*8 + lane>>2][k0, k0+1],
//   k0 = k16*16 + reg*8 + 2*(lane&3).  Layout [k16][lane][f].
// =====================================================================
static __device__ __forceinline__ void prep_body(const float* __restrict__ src, int t4)
{
    int lane = t4 & 31;
    int f    = (t4 >> 5) & 7;
    int k16b = (t4 >> 8) * 4;
    int reg  = f & 1;
    int nt   = f >> 1;
    int n    = nt * 8 + (lane >> 2);
    const bool ok = (n < N_NODES);
    const float* row = src + (size_t)n * K_DIM;
    float f0[4], f1[4];
    #pragma unroll
    for (int u = 0; u < 4; u++) {
        int k0 = (k16b + u) * 16 + reg * 8 + 2 * (lane & 3);
        f0[u] = ok ? row[k0]     : 0.0f;
        f1[u] = ok ? row[k0 + 1] : 0.0f;
    }
    #pragma unroll
    for (int u = 0; u < 4; u++) {
        uint32_t hi, lo;
        split_pack(f0[u], f1[u], hi, lo);
        int idx = (k16b + u) * 256 + lane * 8 + f;
        g_bhi[idx] = hi;
        g_blo[idx] = lo;
    }
}

// =====================================================================
// pre: blocks [0,80) prep node frags | [80,134) granger dots | rest init
// =====================================================================
__global__ __launch_bounds__(256)
void pre_kernel(const float* __restrict__ node, const float* __restrict__ hist,
                const float* __restrict__ gw, const float* __restrict__ inb,
                const float* __restrict__ outb, const int* __restrict__ lh,
                float* __restrict__ out)
{
    const int bx = blockIdx.x;
    const int tid = threadIdx.x;

    if (bx < 80) { prep_body(node, bx * 256 + tid); return; }

    if (bx < 134) {   // granger dot b (0..53)
        const int b = bx - 80;
        const float* x  = (b < 27) ? node + (size_t)b * E_DIM : hist + (size_t)(b - 27) * E_DIM;
        const float* wv = (b < 27) ? gw + E_DIM : gw;
        float s = 0.0f;
        for (int k = tid; k < E_DIM; k += 256) s += x[k] * wv[k];
        __shared__ float sred[8];
        #pragma unroll
        for (int off = 16; off; off >>= 1) s += __shfl_xor_sync(0xffffffffu, s, off);
        if ((tid & 31) == 0) sred[tid >> 5] = s;
        __syncthreads();
        if (tid < 8) {
            s = sred[tid];
            #pragma unroll
            for (int off = 4; off; off >>= 1) s += __shfl_xor_sync(0x000000ffu, s, off);
            if (tid == 0) g_colrow[b] = s;
        }
        return;
    }

    int t = (bx - 134) * 256 + tid;
    if (t < 15360 * 27) {                       // qkvT bias seed
        int m = t / 27, n = t - m * 27;
        g_qkvT[m * 28 + n] = inb[m];
    } else if (t < 15360 * 27 + 27 * 5120) {    // out bias*hw seed
        int t2 = t - 15360 * 27;
        out[t2] = outb[t2 % 5120] * hw_from(lh);
    } else if (t < 15360 * 27 + 27 * 5120 + 4 * 729) {
        g_scores[t - (15360 * 27 + 27 * 5120)] = 0.0f;
    } else if (t == 15360 * 27 + 27 * 5120 + 4 * 729) {
        g_cnt = 0;
        g_flag = 0;
    }
}

// =====================================================================
// Barrier-free HMMA split-K GEMM, 48 rows/warp (3 m-frags), occ 3:
//   D[m][n] = sum_k W[m][k] * X[n][k]
//   128 thr = 4 warps x 48 rows = 192 rows/CTA.
//   A: dist-2 register prefetch (DRAM), 6 clamped row pointers.
//   B: dist-1 register prefetch from L2 frags (LDG.128 x4).
// =====================================================================
#define MF 3

template<int BUF>
static __device__ __forceinline__ void gstep(
    int& i, int nk16, int k16_0, const float* const (&rp)[2 * MF], int lane,
    float2 (&Ast)[2][4 * MF], uint32_t (&Bh)[2][8], uint32_t (&Bl)[2][8],
    float (&acc)[MF][4][4])
{
    constexpr int NBUF = BUF ^ 1;
    // B prefetch for i+1 (L2 hit, one full k16 of slack)
    if (i + 1 < nk16) {
        const uint32_t* ph = g_bhi + (size_t)(k16_0 + i + 1) * 256 + lane * 8;
        const uint32_t* pl = g_blo + (size_t)(k16_0 + i + 1) * 256 + lane * 8;
        uint4 h0 = *(const uint4*)ph, h1 = *(const uint4*)(ph + 4);
        uint4 l0 = *(const uint4*)pl, l1 = *(const uint4*)(pl + 4);
        Bh[NBUF][0] = h0.x; Bh[NBUF][1] = h0.y; Bh[NBUF][2] = h0.z; Bh[NBUF][3] = h0.w;
        Bh[NBUF][4] = h1.x; Bh[NBUF][5] = h1.y; Bh[NBUF][6] = h1.z; Bh[NBUF][7] = h1.w;
        Bl[NBUF][0] = l0.x; Bl[NBUF][1] = l0.y; Bl[NBUF][2] = l0.z; Bl[NBUF][3] = l0.w;
        Bl[NBUF][4] = l1.x; Bl[NBUF][5] = l1.y; Bl[NBUF][6] = l1.z; Bl[NBUF][7] = l1.w;
    }
    // convert staged A (loads issued at i-2)
    uint32_t ahi[MF][4], alo[MF][4];
    #pragma unroll
    for (int q = 0; q < 4 * MF; q++)
        split_pack(Ast[BUF][q].x, Ast[BUF][q].y, ahi[q >> 2][q & 3], alo[q >> 2][q & 3]);
    // A prefetch for i+2 into freed buffer
    if (i + 2 < nk16) {
        #pragma unroll
        for (int mf = 0; mf < MF; mf++)
            #pragma unroll
            for (int kc = 0; kc < 2; kc++)
                #pragma unroll
                for (int rr = 0; rr < 2; rr++)
                    Ast[BUF][mf * 4 + kc * 2 + rr] =
                        *(const float2*)(rp[mf * 2 + rr] + (size_t)(i + 2) * 16 + kc * 8);
    }
    #pragma unroll
    for (int mf = 0; mf < MF; mf++)
        #pragma unroll
        for (int nt = 0; nt < 4; nt++) {
            MMA_BF16(acc[mf][nt], ahi[mf], Bh[BUF][nt * 2], Bh[BUF][nt * 2 + 1]);
            MMA_BF16(acc[mf][nt], ahi[mf], Bl[BUF][nt * 2], Bl[BUF][nt * 2 + 1]);
            MMA_BF16(acc[mf][nt], alo[mf], Bh[BUF][nt * 2], Bh[BUF][nt * 2 + 1]);
        }
    i++;
}

__global__ __launch_bounds__(128, 3)
void gemm_hmma(const float* __restrict__ W, float* __restrict__ dst,
               int mode, int spl16, int Mmax, const int* __restrict__ lh)
{
    const int tid  = threadIdx.x;
    const int lane = tid & 31;
    const int wid  = tid >> 5;
    const int mbase = blockIdx.x * (4 * 16 * MF) + wid * (16 * MF);
    const int k16_0 = blockIdx.y * spl16;
    const int nk16  = min(spl16, 320 - k16_0);
    const int r  = lane >> 2;
    const int t2 = (lane & 3) * 2;

    // clamped row pointers (rows beyond Mmax load row Mmax-1; stores guarded)
    const float* rp[2 * MF];
    #pragma unroll
    for (int mf = 0; mf < MF; mf++)
        #pragma unroll
        for (int rr = 0; rr < 2; rr++) {
            int row = mbase + mf * 16 + rr * 8 + r;
            row = (row < Mmax) ? row : (Mmax - 1);
            rp[mf * 2 + rr] = W + (size_t)row * K_DIM + (size_t)k16_0 * 16 + t2;
        }

    float acc[MF][4][4];
    #pragma unroll
    for (int mf = 0; mf < MF; mf++)
        #pragma unroll
        for (int nt = 0; nt < 4; nt++)
            #pragma unroll
            for (int q = 0; q < 4; q++) acc[mf][nt][q] = 0.0f;

    float2   Ast[2][4 * MF];
    uint32_t Bh[2][8], Bl[2][8];

    // prologue: A(0)->buf0, A(1)->buf1, B(0)->buf0
    #pragma unroll
    for (int mf = 0; mf < MF; mf++)
        #pragma unroll
        for (int kc = 0; kc < 2; kc++)
            #pragma unroll
            for (int rr = 0; rr < 2; rr++)
                Ast[0][mf * 4 + kc * 2 + rr] = *(const float2*)(rp[mf * 2 + rr] + kc * 8);
    if (nk16 > 1) {
        #pragma unroll
        for (int mf = 0; mf < MF; mf++)
            #pragma unroll
            for (int kc = 0; kc < 2; kc++)
                #pragma unroll
                for (int rr = 0; rr < 2; rr++)
                    Ast[1][mf * 4 + kc * 2 + rr] = *(const float2*)(rp[mf * 2 + rr] + 16 + kc * 8);
    }
    {
        const uint32_t* ph = g_bhi + (size_t)k16_0 * 256 + lane * 8;
        const uint32_t* pl = g_blo + (size_t)k16_0 * 256 + lane * 8;
        uint4 h0 = *(const uint4*)ph, h1 = *(const uint4*)(ph + 4);
        uint4 l0 = *(const uint4*)pl, l1 = *(const uint4*)(pl + 4);
        Bh[0][0] = h0.x; Bh[0][1] = h0.y; Bh[0][2] = h0.z; Bh[0][3] = h0.w;
        Bh[0][4] = h1.x; Bh[0][5] = h1.y; Bh[0][6] = h1.z; Bh[0][7] = h1.w;
        Bl[0][0] = l0.x; Bl[0][1] = l0.y; Bl[0][2] = l0.z; Bl[0][3] = l0.w;
        Bl[0][4] = l1.x; Bl[0][5] = l1.y; Bl[0][6] = l1.z; Bl[0][7] = l1.w;
    }

    int i = 0;
    while (true) {
        gstep<0>(i, nk16, k16_0, rp, lane, Ast, Bh, Bl, acc);
        if (i >= nk16) break;
        gstep<1>(i, nk16, k16_0, rp, lane, Ast, Bh, Bl, acc);
        if (i >= nk16) break;
    }

    // epilogue: d0=(m0,n0) d1=(m0,n0+1) d2=(m0+8,n0) d3=(m0+8,n0+1)
    if (mode == 0) {
        #pragma unroll
        for (int mf = 0; mf < MF; mf++) {
            int m0 = mbase + mf * 16 + r;
            #pragma unroll
            for (int nt = 0; nt < 4; nt++) {
                int n0 = nt * 8 + t2;
                if (n0 < N_NODES)     atomicAdd(&g_qkvT[m0 * 28 + n0],           acc[mf][nt][0]);
                if (n0 + 1 < N_NODES) atomicAdd(&g_qkvT[m0 * 28 + n0 + 1],       acc[mf][nt][1]);
                if (n0 < N_NODES)     atomicAdd(&g_qkvT[(m0 + 8) * 28 + n0],     acc[mf][nt][2]);
                if (n0 + 1 < N_NODES) atomicAdd(&g_qkvT[(m0 + 8) * 28 + n0 + 1], acc[mf][nt][3]);
            }
        }
    } else {
        const float hw = hw_from(lh);
        #pragma unroll
        for (int mf = 0; mf < MF; mf++) {
            int m0 = mbase + mf * 16 + r;
            const bool ok0 = (m0 < Mmax), ok8 = (m0 + 8 < Mmax);
            #pragma unroll
            for (int nt = 0; nt < 4; nt++) {
                int n0 = nt * 8 + t2;
                if (ok0 && n0 < N_NODES)     atomicAdd(&dst[(size_t)n0 * E_DIM + m0],           acc[mf][nt][0] * hw);
                if (ok0 && n0 + 1 < N_NODES) atomicAdd(&dst[(size_t)(n0 + 1) * E_DIM + m0],     acc[mf][nt][1] * hw);
                if (ok8 && n0 < N_NODES)     atomicAdd(&dst[(size_t)n0 * E_DIM + m0 + 8],       acc[mf][nt][2] * hw);
                if (ok8 && n0 + 1 < N_NODES) atomicAdd(&dst[(size_t)(n0 + 1) * E_DIM + m0 + 8], acc[mf][nt][3] * hw);
            }
        }
    }
}

// =====================================================================
// Fused attention: scores partials -> counter -> last-block softmax+adj
// -> flag -> all blocks AV + GEMM2 fragment emission.
// grid (10,4); 40 blocks << 148 SMs -> all resident, spin-wait safe.
// =====================================================================
__global__ __launch_bounds__(256)
void attn_fused(const float* __restrict__ gb, float* __restrict__ out)
{
    const int ct = blockIdx.x;   // 0..9
    const int h  = blockIdx.y;   // 0..3
    __shared__ float sA[128 * 29];   // q tile, then v tile
    __shared__ float sB[128 * 29];   // k tile, then o (stride 28)
    __shared__ float sa[729];
    const int tid = threadIdx.x;

    const float4* qb = (const float4*)(g_qkvT + (size_t)(h * HD + ct * 128) * 28);
    const float4* kb = (const float4*)(g_qkvT + (size_t)(E_DIM + h * HD + ct * 128) * 28);
    for (int idx = tid; idx < 896; idx += 256) {
        int c = idx / 7, r4 = idx - c * 7;
        float4 q4 = qb[idx], k4 = kb[idx];
        int b = c * 29 + r4 * 4;
        sA[b] = q4.x; sA[b + 1] = q4.y; sA[b + 2] = q4.z; sA[b + 3] = q4.w;
        sB[b] = k4.x; sB[b + 1] = k4.y; sB[b + 2] = k4.z; sB[b + 3] = k4.w;
    }
    __syncthreads();

    for (int t = tid; t < 729; t += 256) {
        int i = t / 27, j = t - i * 27;
        float s0 = 0.0f, s1 = 0.0f;
        #pragma unroll
        for (int c = 0; c < 128; c += 2) {
            s0 += sA[c * 29 + i] * sB[c * 29 + j];
            s1 += sA[(c + 1) * 29 + i] * sB[(c + 1) * 29 + j];
        }
        atomicAdd(&g_scores[h * 729 + t], s0 + s1);
    }
    __threadfence();
    __syncthreads();

    __shared__ int isLast;
    if (tid == 0) isLast = (atomicAdd(&g_cnt, 1) == 39);
    __syncthreads();

    // overwrite sA with V tile while waiting (q/k no longer needed)
    const float4* vb = (const float4*)(g_qkvT + (size_t)(2 * E_DIM + h * HD + ct * 128) * 28);
    for (int idx = tid; idx < 896; idx += 256) {
        int c = idx / 7, r4 = idx - c * 7;
        float4 v4 = vb[idx];
        int b = c * 29 + r4 * 4;
        sA[b] = v4.x; sA[b + 1] = v4.y; sA[b + 2] = v4.z; sA[b + 3] = v4.w;
    }

    if (isLast) {
        if (tid < 108) {   // softmax per (head, query)
            const int hh = tid / 27, i = tid - hh * 27;
            const float scale = rsqrtf((float)HD);
            const float* sc = g_scores + hh * 729 + i * 27;
            float mx = -1e30f;
            #pragma unroll
            for (int j = 0; j < 27; j++) mx = fmaxf(mx, sc[j] * scale);
            float e[27], sum = 0.0f;
            #pragma unroll
            for (int j = 0; j < 27; j++) { e[j] = expf(sc[j] * scale - mx); sum += e[j]; }
            const float inv = 1.0f / sum;
            float* at = g_attn + hh * 729 + i * 27;
            #pragma unroll
            for (int j = 0; j < 27; j++) at[j] = e[j] * inv;
        }
        for (int idx = tid; idx < 729; idx += 256) {   // causal adjacency
            int i = idx / 27, j = idx - i * 27;
            float v = 0.0f;
            if (i != j)
                v = 1.0f / (1.0f + expf(-(g_colrow[i] + g_colrow[27 + j] + gb[0])));
            out[N_NODES * E_DIM + idx] = v;
        }
        __syncthreads();
        __threadfence();
        if (tid == 0) *(volatile int*)&g_flag = 1;
    }

    if (tid == 0) { while (*(volatile int*)&g_flag == 0) { } }
    __syncthreads();
    __threadfence();

    for (int idx = tid; idx < 729; idx += 256) sa[idx] = g_attn[h * 729 + idx];
    __syncthreads();

    // AV into sB (o[c][i], stride 28)
    for (int f = tid; f < 27 * 128; f += 256) {
        int c = f & 127, i = f >> 7;
        float o = 0.0f;
        #pragma unroll
        for (int j = 0; j < 27; j++) o += sa[i * 27 + j] * sA[c * 29 + j];
        sB[c * 28 + i] = o;
    }
    __syncthreads();

    // GEMM2 fragment emission ([k16][lane][f] layout)
    const int k16g0 = (h * HD + ct * 128) >> 4;
    const int lane = tid & 31;
    const int f    = tid >> 5;          // 0..7
    const int nt   = f >> 1, reg = f & 1;
    const int n    = nt * 8 + (lane >> 2);
    const int cb   = reg * 8 + 2 * (lane & 3);
    const bool ok  = (n < N_NODES);
    #pragma unroll
    for (int k16l = 0; k16l < 8; k16l++) {
        int c = k16l * 16 + cb;
        float f0 = ok ? sB[c * 28 + n]       : 0.0f;
        float f1 = ok ? sB[(c + 1) * 28 + n] : 0.0f;
        uint32_t hi, lo;
        split_pack(f0, f1, hi, lo);
        int idx = (k16g0 + k16l) * 256 + lane * 8 + f;
        g_bhi[idx] = hi;
        g_blo[idx] = lo;
    }
}

// =====================================================================
extern "C" void kernel_launch(void* const* d_in, const int* in_sizes, int n_in,
                              void* d_out, int out_size)
{
    const float* node = (const float*)d_in[0];
    const float* hist = (const float*)d_in[1];
    const float* gw   = (const float*)d_in[2];
    const float* gb   = (const float*)d_in[3];
    const float* inw  = (const float*)d_in[4];
    const float* inb  = (const float*)d_in[5];
    const float* outw = (const float*)d_in[6];
    const float* outb = (const float*)d_in[7];
    const int*   lh   = (const int*)d_in[8];
    float* out = (float*)d_out;

    const int init_elems = 15360 * 27 + 27 * 5120 + 4 * 729 + 1;
    const int init_blocks = (init_elems + 255) / 256;
    pre_kernel<<<134 + init_blocks, 256>>>(node, hist, gw, inb, outb, lh, out);

    // qkv += x @ in_proj_w^T : 80 M-tiles (192 rows) x 5 K-splits (64 k16)
    gemm_hmma<<<dim3(80, 5), 128>>>(inw, nullptr, 0, 64, 15360, lh);

    attn_fused<<<dim3(10, 4), 256>>>(gb, out);

    // out += (o @ out_proj_w^T) * hw : 27 M-tiles x 16 K-splits (20 k16)
    gemm_hmma<<<dim3(27, 16), 128>>>(outw, out, 1, 20, 5120, lh);
}

// round 13
// speedup vs baseline: 1.5706x; 1.0455x over previous
#include <cuda_runtime.h>
#include <cstdint>

#define K_DIM   5120
#define E_DIM   5120
#define N_NODES 27
#define HD      1280

// ---- scratch (device globals; no allocations allowed) ----
__device__ float    g_qkvT[15360 * 28];    // qkv transposed [3E][28]
__device__ float    g_colrow[54];
__device__ float    g_scores[4 * 729];
__device__ float    g_attn[4 * 729];
__device__ int      g_cnt;
__device__ int      g_flag;
// B operand, PERMUTED k-slot order: [k16 (320)][lane (32)][frag (8 = nt*2+reg)]
//   lane group q = lane&3 owns physical k {4q..4q+3}:
//   reg0 = (k16*16+4q, +1), reg1 = (k16*16+4q+2, +3)
__device__ uint32_t g_bhi[320 * 256];
__device__ uint32_t g_blo[320 * 256];

static __device__ __forceinline__ float hw_from(const int* lh) {
    int iv = *lh;
    float f = (iv > 0 && iv < 100000000) ? (float)iv : __int_as_float(iv);
    return fminf(fmaxf(f * 0.001f, 0.1f), 1.0f);
}

// Split f32 pair -> bf16x2 hi (exact truncation) + bf16x2 lo (rounded remainder).
static __device__ __forceinline__ void split_pack(float f0, float f1,
                                                  uint32_t& hi, uint32_t& lo) {
    uint32_t u0 = __float_as_uint(f0), u1 = __float_as_uint(f1);
    asm("prmt.b32 %0, %1, %2, 0x7632;" : "=r"(hi) : "r"(u0), "r"(u1));
    float l0 = f0 - __uint_as_float(u0 & 0xFFFF0000u);
    float l1 = f1 - __uint_as_float(u1 & 0xFFFF0000u);
    asm("cvt.rn.bf16x2.f32 %0, %1, %2;" : "=r"(lo) : "f"(l1), "f"(l0));
}

#define MMA_BF16(d, a, b0, b1)                                                  \
    asm volatile(                                                               \
        "mma.sync.aligned.m16n8k16.row.col.f32.bf16.bf16.f32 "                  \
        "{%0,%1,%2,%3}, {%4,%5,%6,%7}, {%8,%9}, {%0,%1,%2,%3};"                 \
        : "+f"((d)[0]), "+f"((d)[1]), "+f"((d)[2]), "+f"((d)[3])                \
        : "r"((a)[0]), "r"((a)[1]), "r"((a)[2]), "r"((a)[3]),                   \
          "r"(b0), "r"(b1))

// =====================================================================
// Fragment prep for X (27 x 5120), permuted slots, float4 loads:
//   thread (lane, nt) -> n = nt*8 + lane>>2, one float4 per k16:
//   v = X[n][k16*16 + 4*(lane&3) .. +3]; reg0=(v.x,v.y), reg1=(v.z,v.w).
//   4 k16 per thread.
// =====================================================================
static __device__ __forceinline__ void prep_body(const float* __restrict__ src, int t4)
{
    int lane = t4 & 31;
    int nt   = (t4 >> 5) & 3;
    int k16b = (t4 >> 7) * 4;
    int n    = nt * 8 + (lane >> 2);
    const bool ok = (n < N_NODES);
    const float* row = src + (size_t)n * K_DIM + 4 * (lane & 3);
    float4 v[4];
    #pragma unroll
    for (int u = 0; u < 4; u++)
        v[u] = ok ? *(const float4*)(row + (size_t)(k16b + u) * 16)
                  : make_float4(0.f, 0.f, 0.f, 0.f);
    #pragma unroll
    for (int u = 0; u < 4; u++) {
        uint32_t h0, l0, h1, l1;
        split_pack(v[u].x, v[u].y, h0, l0);
        split_pack(v[u].z, v[u].w, h1, l1);
        int idx = (k16b + u) * 256 + lane * 8 + nt * 2;
        *(uint2*)(g_bhi + idx) = make_uint2(h0, h1);
        *(uint2*)(g_blo + idx) = make_uint2(l0, l1);
    }
}

// =====================================================================
// pre: blocks [0,40) prep node frags | [40,94) granger dots | rest init
// =====================================================================
__global__ __launch_bounds__(256)
void pre_kernel(const float* __restrict__ node, const float* __restrict__ hist,
                const float* __restrict__ gw, const float* __restrict__ inb,
                const float* __restrict__ outb, const int* __restrict__ lh,
                float* __restrict__ out)
{
    const int bx = blockIdx.x;
    const int tid = threadIdx.x;

    if (bx < 40) { prep_body(node, bx * 256 + tid); return; }

    if (bx < 94) {   // granger dot b (0..53)
        const int b = bx - 40;
        const float* x  = (b < 27) ? node + (size_t)b * E_DIM : hist + (size_t)(b - 27) * E_DIM;
        const float* wv = (b < 27) ? gw + E_DIM : gw;
        float s = 0.0f;
        for (int k = tid; k < E_DIM; k += 256) s += x[k] * wv[k];
        __shared__ float sred[8];
        #pragma unroll
        for (int off = 16; off; off >>= 1) s += __shfl_xor_sync(0xffffffffu, s, off);
        if ((tid & 31) == 0) sred[tid >> 5] = s;
        __syncthreads();
        if (tid < 8) {
            s = sred[tid];
            #pragma unroll
            for (int off = 4; off; off >>= 1) s += __shfl_xor_sync(0x000000ffu, s, off);
            if (tid == 0) g_colrow[b] = s;
        }
        return;
    }

    int t = (bx - 94) * 256 + tid;
    if (t < 15360 * 27) {                       // qkvT bias seed
        int m = t / 27, n = t - m * 27;
        g_qkvT[m * 28 + n] = inb[m];
    } else if (t < 15360 * 27 + 27 * 5120) {    // out bias*hw seed
        int t2 = t - 15360 * 27;
        out[t2] = outb[t2 % 5120] * hw_from(lh);
    } else if (t < 15360 * 27 + 27 * 5120 + 4 * 729) {
        g_scores[t - (15360 * 27 + 27 * 5120)] = 0.0f;
    } else if (t == 15360 * 27 + 27 * 5120 + 4 * 729) {
        g_cnt = 0;
        g_flag = 0;
    }
}

// =====================================================================
// Barrier-free HMMA split-K GEMM, 48 rows/warp (3 m-frags), occ 3:
//   D[m][n] = sum_k W[m][k] * X[n][k]
//   A: dist-2 register prefetch, ONE float4 (LDG.128) per row per k16
//      (permuted k-slots). B: dist-1 LDG.128 x4 from L2 frags.
// =====================================================================
#define MF 3

template<int BUF>
static __device__ __forceinline__ void gstep(
    int& i, int nk16, int k16_0, const float* const (&rp)[2 * MF], int lane,
    float4 (&Ast)[2][2 * MF], uint32_t (&Bh)[2][8], uint32_t (&Bl)[2][8],
    float (&acc)[MF][4][4])
{
    constexpr int NBUF = BUF ^ 1;
    // B prefetch for i+1 (L2 hit, one full k16 of slack)
    if (i + 1 < nk16) {
        const uint32_t* ph = g_bhi + (size_t)(k16_0 + i + 1) * 256 + lane * 8;
        const uint32_t* pl = g_blo + (size_t)(k16_0 + i + 1) * 256 + lane * 8;
        uint4 h0 = *(const uint4*)ph, h1 = *(const uint4*)(ph + 4);
        uint4 l0 = *(const uint4*)pl, l1 = *(const uint4*)(pl + 4);
        Bh[NBUF][0] = h0.x; Bh[NBUF][1] = h0.y; Bh[NBUF][2] = h0.z; Bh[NBUF][3] = h0.w;
        Bh[NBUF][4] = h1.x; Bh[NBUF][5] = h1.y; Bh[NBUF][6] = h1.z; Bh[NBUF][7] = h1.w;
        Bl[NBUF][0] = l0.x; Bl[NBUF][1] = l0.y; Bl[NBUF][2] = l0.z; Bl[NBUF][3] = l0.w;
        Bl[NBUF][4] = l1.x; Bl[NBUF][5] = l1.y; Bl[NBUF][6] = l1.z; Bl[NBUF][7] = l1.w;
    }
    // convert staged A (loads issued at i-2); slot map: a[rr]=reg0, a[2+rr]=reg1
    uint32_t ahi[MF][4], alo[MF][4];
    #pragma unroll
    for (int q = 0; q < 2 * MF; q++) {
        const int mf = q >> 1, rr = q & 1;
        split_pack(Ast[BUF][q].x, Ast[BUF][q].y, ahi[mf][rr],     alo[mf][rr]);
        split_pack(Ast[BUF][q].z, Ast[BUF][q].w, ahi[mf][2 + rr], alo[mf][2 + rr]);
    }
    // A prefetch for i+2 into freed buffer (one LDG.128 per row)
    if (i + 2 < nk16) {
        #pragma unroll
        for (int q = 0; q < 2 * MF; q++)
            Ast[BUF][q] = *(const float4*)(rp[q] + (size_t)(i + 2) * 16);
    }
    #pragma unroll
    for (int mf = 0; mf < MF; mf++)
        #pragma unroll
        for (int nt = 0; nt < 4; nt++) {
            MMA_BF16(acc[mf][nt], ahi[mf], Bh[BUF][nt * 2], Bh[BUF][nt * 2 + 1]);
            MMA_BF16(acc[mf][nt], ahi[mf], Bl[BUF][nt * 2], Bl[BUF][nt * 2 + 1]);
            MMA_BF16(acc[mf][nt], alo[mf], Bh[BUF][nt * 2], Bh[BUF][nt * 2 + 1]);
        }
    i++;
}

__global__ __launch_bounds__(128, 3)
void gemm_hmma(const float* __restrict__ W, float* __restrict__ dst,
               int mode, int spl16, int Mmax, const int* __restrict__ lh)
{
    const int tid  = threadIdx.x;
    const int lane = tid & 31;
    const int wid  = tid >> 5;
    const int mbase = blockIdx.x * (4 * 16 * MF) + wid * (16 * MF);
    const int k16_0 = blockIdx.y * spl16;
    const int nk16  = min(spl16, 320 - k16_0);
    const int r  = lane >> 2;
    const int t4 = (lane & 3) * 4;

    // clamped row pointers (rows beyond Mmax load row Mmax-1; stores guarded)
    const float* rp[2 * MF];
    #pragma unroll
    for (int mf = 0; mf < MF; mf++)
        #pragma unroll
        for (int rr = 0; rr < 2; rr++) {
            int row = mbase + mf * 16 + rr * 8 + r;
            row = (row < Mmax) ? row : (Mmax - 1);
            rp[mf * 2 + rr] = W + (size_t)row * K_DIM + (size_t)k16_0 * 16 + t4;
        }

    float acc[MF][4][4];
    #pragma unroll
    for (int mf = 0; mf < MF; mf++)
        #pragma unroll
        for (int nt = 0; nt < 4; nt++)
            #pragma unroll
            for (int q = 0; q < 4; q++) acc[mf][nt][q] = 0.0f;

    float4   Ast[2][2 * MF];
    uint32_t Bh[2][8], Bl[2][8];

    // prologue: A(0)->buf0, A(1)->buf1, B(0)->buf0
    #pragma unroll
    for (int q = 0; q < 2 * MF; q++)
        Ast[0][q] = *(const float4*)(rp[q]);
    if (nk16 > 1) {
        #pragma unroll
        for (int q = 0; q < 2 * MF; q++)
            Ast[1][q] = *(const float4*)(rp[q] + 16);
    }
    {
        const uint32_t* ph = g_bhi + (size_t)k16_0 * 256 + lane * 8;
        const uint32_t* pl = g_blo + (size_t)k16_0 * 256 + lane * 8;
        uint4 h0 = *(const uint4*)ph, h1 = *(const uint4*)(ph + 4);
        uint4 l0 = *(const uint4*)pl, l1 = *(const uint4*)(pl + 4);
        Bh[0][0] = h0.x; Bh[0][1] = h0.y; Bh[0][2] = h0.z; Bh[0][3] = h0.w;
        Bh[0][4] = h1.x; Bh[0][5] = h1.y; Bh[0][6] = h1.z; Bh[0][7] = h1.w;
        Bl[0][0] = l0.x; Bl[0][1] = l0.y; Bl[0][2] = l0.z; Bl[0][3] = l0.w;
        Bl[0][4] = l1.x; Bl[0][5] = l1.y; Bl[0][6] = l1.z; Bl[0][7] = l1.w;
    }

    int i = 0;
    while (true) {
        gstep<0>(i, nk16, k16_0, rp, lane, Ast, Bh, Bl, acc);
        if (i >= nk16) break;
        gstep<1>(i, nk16, k16_0, rp, lane, Ast, Bh, Bl, acc);
        if (i >= nk16) break;
    }

    // epilogue: d0=(m0,n0) d1=(m0,n0+1) d2=(m0+8,n0) d3=(m0+8,n0+1)
    const int t2 = (lane & 3) * 2;
    if (mode == 0) {
        #pragma unroll
        for (int mf = 0; mf < MF; mf++) {
            int m0 = mbase + mf * 16 + r;
            #pragma unroll
            for (int nt = 0; nt < 4; nt++) {
                int n0 = nt * 8 + t2;
                if (n0 < N_NODES)     atomicAdd(&g_qkvT[m0 * 28 + n0],           acc[mf][nt][0]);
                if (n0 + 1 < N_NODES) atomicAdd(&g_qkvT[m0 * 28 + n0 + 1],       acc[mf][nt][1]);
                if (n0 < N_NODES)     atomicAdd(&g_qkvT[(m0 + 8) * 28 + n0],     acc[mf][nt][2]);
                if (n0 + 1 < N_NODES) atomicAdd(&g_qkvT[(m0 + 8) * 28 + n0 + 1], acc[mf][nt][3]);
            }
        }
    } else {
        const float hw = hw_from(lh);
        #pragma unroll
        for (int mf = 0; mf < MF; mf++) {
            int m0 = mbase + mf * 16 + r;
            const bool ok0 = (m0 < Mmax), ok8 = (m0 + 8 < Mmax);
            #pragma unroll
            for (int nt = 0; nt < 4; nt++) {
                int n0 = nt * 8 + t2;
                if (ok0 && n0 < N_NODES)     atomicAdd(&dst[(size_t)n0 * E_DIM + m0],           acc[mf][nt][0] * hw);
                if (ok0 && n0 + 1 < N_NODES) atomicAdd(&dst[(size_t)(n0 + 1) * E_DIM + m0],     acc[mf][nt][1] * hw);
                if (ok8 && n0 < N_NODES)     atomicAdd(&dst[(size_t)n0 * E_DIM + m0 + 8],       acc[mf][nt][2] * hw);
                if (ok8 && n0 + 1 < N_NODES) atomicAdd(&dst[(size_t)(n0 + 1) * E_DIM + m0 + 8], acc[mf][nt][3] * hw);
            }
        }
    }
}

// =====================================================================
// Fused attention: scores partials -> counter -> last-block softmax+adj
// -> flag -> all blocks AV + GEMM2 fragment emission (permuted slots).
// grid (10,4); 40 blocks << 148 SMs -> all resident, spin-wait safe.
// =====================================================================
__global__ __launch_bounds__(256)
void attn_fused(const float* __restrict__ gb, float* __restrict__ out)
{
    const int ct = blockIdx.x;   // 0..9
    const int h  = blockIdx.y;   // 0..3
    __shared__ float sA[128 * 29];   // q tile, then v tile
    __shared__ float sB[128 * 29];   // k tile, then o (stride 28)
    __shared__ float sa[729];
    const int tid = threadIdx.x;

    const float4* qb = (const float4*)(g_qkvT + (size_t)(h * HD + ct * 128) * 28);
    const float4* kb = (const float4*)(g_qkvT + (size_t)(E_DIM + h * HD + ct * 128) * 28);
    for (int idx = tid; idx < 896; idx += 256) {
        int c = idx / 7, r4 = idx - c * 7;
        float4 q4 = qb[idx], k4 = kb[idx];
        int b = c * 29 + r4 * 4;
        sA[b] = q4.x; sA[b + 1] = q4.y; sA[b + 2] = q4.z; sA[b + 3] = q4.w;
        sB[b] = k4.x; sB[b + 1] = k4.y; sB[b + 2] = k4.z; sB[b + 3] = k4.w;
    }
    __syncthreads();

    for (int t = tid; t < 729; t += 256) {
        int i = t / 27, j = t - i * 27;
        float s0 = 0.0f, s1 = 0.0f;
        #pragma unroll
        for (int c = 0; c < 128; c += 2) {
            s0 += sA[c * 29 + i] * sB[c * 29 + j];
            s1 += sA[(c + 1) * 29 + i] * sB[(c + 1) * 29 + j];
        }
        atomicAdd(&g_scores[h * 729 + t], s0 + s1);
    }
    __threadfence();
    __syncthreads();

    __shared__ int isLast;
    if (tid == 0) isLast = (atomicAdd(&g_cnt, 1) == 39);
    __syncthreads();

    // overwrite sA with V tile while waiting (q/k no longer needed)
    const float4* vb = (const float4*)(g_qkvT + (size_t)(2 * E_DIM + h * HD + ct * 128) * 28);
    for (int idx = tid; idx < 896; idx += 256) {
        int c = idx / 7, r4 = idx - c * 7;
        float4 v4 = vb[idx];
        int b = c * 29 + r4 * 4;
        sA[b] = v4.x; sA[b + 1] = v4.y; sA[b + 2] = v4.z; sA[b + 3] = v4.w;
    }

    if (isLast) {
        if (tid < 108) {   // softmax per (head, query)
            const int hh = tid / 27, i = tid - hh * 27;
            const float scale = rsqrtf((float)HD);
            const float* sc = g_scores + hh * 729 + i * 27;
            float mx = -1e30f;
            #pragma unroll
            for (int j = 0; j < 27; j++) mx = fmaxf(mx, sc[j] * scale);
            float e[27], sum = 0.0f;
            #pragma unroll
            for (int j = 0; j < 27; j++) { e[j] = expf(sc[j] * scale - mx); sum += e[j]; }
            const float inv = 1.0f / sum;
            float* at = g_attn + hh * 729 + i * 27;
            #pragma unroll
            for (int j = 0; j < 27; j++) at[j] = e[j] * inv;
        }
        for (int idx = tid; idx < 729; idx += 256) {   // causal adjacency
            int i = idx / 27, j = idx - i * 27;
            float v = 0.0f;
            if (i != j)
                v = 1.0f / (1.0f + expf(-(g_colrow[i] + g_colrow[27 + j] + gb[0])));
            out[N_NODES * E_DIM + idx] = v;
        }
        __syncthreads();
        __threadfence();
        if (tid == 0) *(volatile int*)&g_flag = 1;
    }

    if (tid == 0) { while (*(volatile int*)&g_flag == 0) { } }
    __syncthreads();
    __threadfence();

    for (int idx = tid; idx < 729; idx += 256) sa[idx] = g_attn[h * 729 + idx];
    __syncthreads();

    // AV into sB (o[c][i], stride 28)
    for (int f = tid; f < 27 * 128; f += 256) {
        int c = f & 127, i = f >> 7;
        float o = 0.0f;
        #pragma unroll
        for (int j = 0; j < 27; j++) o += sa[i * 27 + j] * sA[c * 29 + j];
        sB[c * 28 + i] = o;
    }
    __syncthreads();

    // GEMM2 fragment emission, permuted slots ([k16][lane][nt*2+reg])
    const int k16g0 = (h * HD + ct * 128) >> 4;
    const int lane = tid & 31;
    const int nt8  = tid >> 5;          // 0..7
    const int nt   = nt8 & 3, half = nt8 >> 2;
    const int n    = nt * 8 + (lane >> 2);
    const int cb   = 4 * (lane & 3);
    const bool ok  = (n < N_NODES);
    #pragma unroll
    for (int kl = 0; kl < 4; kl++) {
        int k16l = half * 4 + kl;
        int c = k16l * 16 + cb;
        float f0 = ok ? sB[c * 28 + n]       : 0.0f;
        float f1 = ok ? sB[(c + 1) * 28 + n] : 0.0f;
        float f2 = ok ? sB[(c + 2) * 28 + n] : 0.0f;
        float f3 = ok ? sB[(c + 3) * 28 + n] : 0.0f;
        uint32_t h0, l0, h1, l1;
        split_pack(f0, f1, h0, l0);
        split_pack(f2, f3, h1, l1);
        int idx = (k16g0 + k16l) * 256 + lane * 8 + nt * 2;
        *(uint2*)(g_bhi + idx) = make_uint2(h0, h1);
        *(uint2*)(g_blo + idx) = make_uint2(l0, l1);
    }
}

// =====================================================================
extern "C" void kernel_launch(void* const* d_in, const int* in_sizes, int n_in,
                              void* d_out, int out_size)
{
    const float* node = (const float*)d_in[0];
    const float* hist = (const float*)d_in[1];
    const float* gw   = (const float*)d_in[2];
    const float* gb   = (const float*)d_in[3];
    const float* inw  = (const float*)d_in[4];
    const float* inb  = (const float*)d_in[5];
    const float* outw = (const float*)d_in[6];
    const float* outb = (const float*)d_in[7];
    const int*   lh   = (const int*)d_in[8];
    float* out = (float*)d_out;

    const int init_elems = 15360 * 27 + 27 * 5120 + 4 * 729 + 1;
    const int init_blocks = (init_elems + 255) / 256;
    pre_kernel<<<94 + init_blocks, 256>>>(node, hist, gw, inb, outb, lh, out);

    // qkv += x @ in_proj_w^T : 80 M-tiles (192 rows) x 5 K-splits (64 k16)
    gemm_hmma<<<dim3(80, 5), 128>>>(inw, nullptr, 0, 64, 15360, lh);

    attn_fused<<<dim3(10, 4), 256>>>(gb, out);

    // out += (o @ out_proj_w^T) * hw : 27 M-tiles x 16 K-splits (20 k16)
    gemm_hmma<<<dim3(27, 16), 128>>>(outw, out, 1, 20, 5120, lh);
}